// round 8
// baseline (speedup 1.0000x reference)
#include <cuda_runtime.h>
#include <cuda_fp16.h>
#include <cstdint>
#include <cstddef>

// ---------------------------------------------------------------------------
// GCN_21569325760838: 2-layer GCN, CSR-gather, fp16 tensor-core GEMMs
// (fp32 accum), fp16 intermediates, parallel scan, forked-stream overlap:
//   branch A (legacy): deg -> scan -> scatter
//   branch B (s1):     wcvt -> gemm1 (h1 = x@W1, UNSCALED)
//   join: agg1 applies dinv[s] per gather; then gemm2, agg2.
// ---------------------------------------------------------------------------

#define NMAX 100000
#define EMAX 1600000
#define NF1  128
#define NF2  64
#define SCAN_ELEMS 1024
#define SCAN_NB ((NMAX + SCAN_ELEMS - 1) / SCAN_ELEMS)

__device__ int    g_is64 = 1;
__device__ int    g_deg [NMAX];
__device__ int    g_off [NMAX + 1];
__device__ int    g_cur [NMAX];
__device__ int    g_csr [EMAX];
__device__ int    g_src32[EMAX];
__device__ int    g_dst32[EMAX];
__device__ int    g_bsum[128];
__device__ int    g_boff[128];
__device__ float  g_dinv[NMAX];
__device__ __half g_h1  [(size_t)NMAX * NF1];   // UNSCALED x@W1
__device__ __half g_a1  [(size_t)NMAX * NF1];
__device__ __half g_h2  [(size_t)NMAX * NF2];   // dinv-scaled a1@W2
__device__ __half g_w1t [NF1 * NF1];
__device__ __half g_w2t [NF2 * NF1];

// ---------------------------------------------------------------------------
__global__ void k_init(const long long* __restrict__ p, int nscan, int n) {
    int i = blockIdx.x * blockDim.x + threadIdx.x;
    if (i < n) g_deg[i] = 0;
    if (i < nscan) {
        long long v = p[i];
        if (v < 0 || v >= (long long)n) g_is64 = 0;
    }
}

__device__ __forceinline__ void load_edge(const void* eidx, int e, int E, int& s, int& d) {
    if (g_is64) {
        const long long* p = (const long long*)eidx;
        s = (int)p[e]; d = (int)p[(size_t)E + e];
    } else {
        const int* p = (const int*)eidx;
        s = p[e]; d = p[(size_t)E + e];
    }
}

// Degree histogram + compact int32 edge copy (coalesced).
__global__ void k_deg(const void* __restrict__ eidx, int E) {
    int e = blockIdx.x * blockDim.x + threadIdx.x;
    if (e >= E) return;
    int s, d;
    load_edge(eidx, e, E, s, d);
    g_src32[e] = s;
    g_dst32[e] = d;
    atomicAdd(&g_deg[d], 1);
}

__global__ void k_wcvt(const float* __restrict__ W1, const float* __restrict__ W2) {
    int i = blockIdx.x * blockDim.x + threadIdx.x;
    if (i < NF1 * NF1) {
        int n = i / NF1, k = i % NF1;
        g_w1t[i] = __float2half(W1[(size_t)k * NF1 + n]);
    } else if (i < NF1 * NF1 + NF2 * NF1) {
        int j = i - NF1 * NF1;
        int n = j / NF1, k = j % NF1;
        g_w2t[j] = __float2half(W2[(size_t)k * NF2 + n]);
    }
}

// ---------------------------------------------------------------------------
__global__ void k_scan1(int n) {
    __shared__ int red[256];
    const int t = threadIdx.x;
    int i0 = blockIdx.x * SCAN_ELEMS + t * 4;
    int s = 0;
    #pragma unroll
    for (int k = 0; k < 4; k++) {
        int i = i0 + k;
        if (i < n) s += g_deg[i];
    }
    red[t] = s;
    __syncthreads();
    #pragma unroll
    for (int st = 128; st > 0; st >>= 1) {
        if (t < st) red[t] += red[t + st];
        __syncthreads();
    }
    if (t == 0) g_bsum[blockIdx.x] = red[0];
}

__global__ void k_scan2(int nb) {
    __shared__ int sm[128];
    const int t = threadIdx.x;
    int v = (t < nb) ? g_bsum[t] : 0;
    sm[t] = v;
    __syncthreads();
    #pragma unroll
    for (int st = 1; st < 128; st <<= 1) {
        int u = (t >= st) ? sm[t - st] : 0;
        __syncthreads();
        sm[t] += u;
        __syncthreads();
    }
    g_boff[t] = sm[t] - v;
}

__global__ void k_scan3(int n, int E) {
    __shared__ int sm[256];
    const int t = threadIdx.x;
    const int i0 = blockIdx.x * SCAN_ELEMS + t * 4;
    int vals[4];
    int s = 0;
    #pragma unroll
    for (int k = 0; k < 4; k++) {
        int i = i0 + k;
        vals[k] = (i < n) ? g_deg[i] : 0;
        s += vals[k];
    }
    sm[t] = s;
    __syncthreads();
    #pragma unroll
    for (int st = 1; st < 256; st <<= 1) {
        int u = (t >= st) ? sm[t - st] : 0;
        __syncthreads();
        sm[t] += u;
        __syncthreads();
    }
    int base = g_boff[blockIdx.x] + sm[t] - s;
    #pragma unroll
    for (int k = 0; k < 4; k++) {
        int i = i0 + k;
        if (i < n) {
            g_off[i] = base;
            g_cur[i] = base;
            g_dinv[i] = rsqrtf((float)(vals[k] + 1));
            base += vals[k];
        }
    }
    if (blockIdx.x == 0 && t == 0) g_off[n] = E;
}

// Scatter from compact int32 arrays.
__global__ void k_scatter(int E) {
    int e = blockIdx.x * blockDim.x + threadIdx.x;
    if (e >= E) return;
    int d = g_dst32[e];
    int pos = atomicAdd(&g_cur[d], 1);
    g_csr[pos] = g_src32[e];
}

// ---------------------------------------------------------------------------
// GEMM1: fp16 mma m16n8k16. C fp16 = A_f32[M,128] @ W1  (NO row scaling).
// Block 128x128, 8 warps (2x4), warp tile 64x32.
// ---------------------------------------------------------------------------
__global__ void __launch_bounds__(256, 1)
gemm1_fp16(const float* __restrict__ A, __half* __restrict__ C, int M) {
    constexpr int BM = 128, BN = 128, KC = 32;
    constexpr int K = NF1;
    constexpr int AST = KC + 8;
    constexpr int BST = KC + 8;
    constexpr int WNUM = BN / 32;   // 4
    __shared__ __half As[BM][AST];
    __shared__ __half Bs[BN][BST];

    const int tid  = threadIdx.x;
    const int lane = tid & 31;
    const int warp = tid >> 5;
    const int gid  = lane >> 2;
    const int tig  = lane & 3;
    const int wm   = (warp / WNUM) * 64;
    const int wn   = (warp % WNUM) * 32;
    const int row0 = blockIdx.x * BM;

    float acc[4][4][4];
    #pragma unroll
    for (int mt = 0; mt < 4; mt++)
        #pragma unroll
        for (int nt = 0; nt < 4; nt++)
            #pragma unroll
            for (int i = 0; i < 4; i++) acc[mt][nt][i] = 0.f;

    for (int k0 = 0; k0 < K; k0 += KC) {
        #pragma unroll
        for (int idx = tid; idx < BM * (KC / 4); idx += 256) {
            int r = idx / (KC / 4), c4 = (idx % (KC / 4)) * 4;
            float4 v = make_float4(0.f, 0.f, 0.f, 0.f);
            if (row0 + r < M)
                v = *(const float4*)(A + (size_t)(row0 + r) * K + k0 + c4);
            uint2 o;
            *(__half2*)&o.x = __floats2half2_rn(v.x, v.y);
            *(__half2*)&o.y = __floats2half2_rn(v.z, v.w);
            *(uint2*)&As[r][c4] = o;
        }
        #pragma unroll
        for (int idx = tid; idx < BN * (KC / 4); idx += 256) {
            int n = idx / (KC / 4), c4 = (idx % (KC / 4)) * 4;
            *(uint2*)&Bs[n][c4] = *(const uint2*)(g_w1t + (size_t)n * K + k0 + c4);
        }
        __syncthreads();

        #pragma unroll
        for (int ks = 0; ks < KC / 16; ks++) {
            const int kk = ks * 16;
            uint32_t af[4][4];
            #pragma unroll
            for (int mt = 0; mt < 4; mt++) {
                int rb = wm + mt * 16 + gid;
                af[mt][0] = *(const uint32_t*)&As[rb    ][kk + 2 * tig];
                af[mt][1] = *(const uint32_t*)&As[rb + 8][kk + 2 * tig];
                af[mt][2] = *(const uint32_t*)&As[rb    ][kk + 2 * tig + 8];
                af[mt][3] = *(const uint32_t*)&As[rb + 8][kk + 2 * tig + 8];
            }
            uint32_t bf[4][2];
            #pragma unroll
            for (int nt = 0; nt < 4; nt++) {
                int cb = wn + nt * 8 + gid;
                bf[nt][0] = *(const uint32_t*)&Bs[cb][kk + 2 * tig];
                bf[nt][1] = *(const uint32_t*)&Bs[cb][kk + 2 * tig + 8];
            }
            #pragma unroll
            for (int mt = 0; mt < 4; mt++)
                #pragma unroll
                for (int nt = 0; nt < 4; nt++) {
                    asm volatile(
                        "mma.sync.aligned.m16n8k16.row.col.f32.f16.f16.f32 "
                        "{%0,%1,%2,%3}, {%4,%5,%6,%7}, {%8,%9}, {%0,%1,%2,%3};\n"
                        : "+f"(acc[mt][nt][0]), "+f"(acc[mt][nt][1]),
                          "+f"(acc[mt][nt][2]), "+f"(acc[mt][nt][3])
                        : "r"(af[mt][0]), "r"(af[mt][1]),
                          "r"(af[mt][2]), "r"(af[mt][3]),
                          "r"(bf[nt][0]), "r"(bf[nt][1]));
                }
        }
        __syncthreads();
    }

    #pragma unroll
    for (int mt = 0; mt < 4; mt++) {
        int r0 = row0 + wm + mt * 16 + gid;
        int r1 = r0 + 8;
        #pragma unroll
        for (int nt = 0; nt < 4; nt++) {
            int col = wn + nt * 8 + 2 * tig;
            if (r0 < M)
                *(__half2*)(C + (size_t)r0 * BN + col) =
                    __floats2half2_rn(acc[mt][nt][0], acc[mt][nt][1]);
            if (r1 < M)
                *(__half2*)(C + (size_t)r1 * BN + col) =
                    __floats2half2_rn(acc[mt][nt][2], acc[mt][nt][3]);
        }
    }
}

// ---------------------------------------------------------------------------
// GEMM2: fp16 mma m16n8k16, C fp16 = rowscale[m]*(A_f16[M,128] @ W2).
// Block 256x64, 8 warps (4x2), warp tile 64x32.
// ---------------------------------------------------------------------------
__global__ void __launch_bounds__(256, 1)
gemm2_fp16(const __half* __restrict__ A, __half* __restrict__ C,
           const float* __restrict__ rowscale, int M) {
    constexpr int BM = 256, BN = 64, KC = 32;
    constexpr int K = NF1;
    constexpr int AST = KC + 8;
    constexpr int BST = KC + 8;
    constexpr int WNUM = BN / 32;  // 2
    __shared__ __half As[BM][AST];
    __shared__ __half Bs[BN][BST];

    const int tid  = threadIdx.x;
    const int lane = tid & 31;
    const int warp = tid >> 5;
    const int gid  = lane >> 2;
    const int tig  = lane & 3;
    const int wm   = (warp / WNUM) * 64;
    const int wn   = (warp % WNUM) * 32;
    const int row0 = blockIdx.x * BM;

    float acc[4][4][4];
    #pragma unroll
    for (int mt = 0; mt < 4; mt++)
        #pragma unroll
        for (int nt = 0; nt < 4; nt++)
            #pragma unroll
            for (int i = 0; i < 4; i++) acc[mt][nt][i] = 0.f;

    for (int k0 = 0; k0 < K; k0 += KC) {
        #pragma unroll
        for (int idx = tid; idx < BM * (KC / 4); idx += 256) {
            int r = idx / (KC / 4), c4 = (idx % (KC / 4)) * 4;
            uint2 v = make_uint2(0u, 0u);
            if (row0 + r < M)
                v = *(const uint2*)(A + (size_t)(row0 + r) * K + k0 + c4);
            *(uint2*)&As[r][c4] = v;
        }
        #pragma unroll
        for (int idx = tid; idx < BN * (KC / 4); idx += 256) {
            int n = idx / (KC / 4), c4 = (idx % (KC / 4)) * 4;
            *(uint2*)&Bs[n][c4] = *(const uint2*)(g_w2t + (size_t)n * K + k0 + c4);
        }
        __syncthreads();

        #pragma unroll
        for (int ks = 0; ks < KC / 16; ks++) {
            const int kk = ks * 16;
            uint32_t af[4][4];
            #pragma unroll
            for (int mt = 0; mt < 4; mt++) {
                int rb = wm + mt * 16 + gid;
                af[mt][0] = *(const uint32_t*)&As[rb    ][kk + 2 * tig];
                af[mt][1] = *(const uint32_t*)&As[rb + 8][kk + 2 * tig];
                af[mt][2] = *(const uint32_t*)&As[rb    ][kk + 2 * tig + 8];
                af[mt][3] = *(const uint32_t*)&As[rb + 8][kk + 2 * tig + 8];
            }
            uint32_t bf[4][2];
            #pragma unroll
            for (int nt = 0; nt < 4; nt++) {
                int cb = wn + nt * 8 + gid;
                bf[nt][0] = *(const uint32_t*)&Bs[cb][kk + 2 * tig];
                bf[nt][1] = *(const uint32_t*)&Bs[cb][kk + 2 * tig + 8];
            }
            #pragma unroll
            for (int mt = 0; mt < 4; mt++)
                #pragma unroll
                for (int nt = 0; nt < 4; nt++) {
                    asm volatile(
                        "mma.sync.aligned.m16n8k16.row.col.f32.f16.f16.f32 "
                        "{%0,%1,%2,%3}, {%4,%5,%6,%7}, {%8,%9}, {%0,%1,%2,%3};\n"
                        : "+f"(acc[mt][nt][0]), "+f"(acc[mt][nt][1]),
                          "+f"(acc[mt][nt][2]), "+f"(acc[mt][nt][3])
                        : "r"(af[mt][0]), "r"(af[mt][1]),
                          "r"(af[mt][2]), "r"(af[mt][3]),
                          "r"(bf[nt][0]), "r"(bf[nt][1]));
                }
        }
        __syncthreads();
    }

    #pragma unroll
    for (int mt = 0; mt < 4; mt++) {
        int r0 = row0 + wm + mt * 16 + gid;
        int r1 = r0 + 8;
        #pragma unroll
        for (int nt = 0; nt < 4; nt++) {
            int col = wn + nt * 8 + 2 * tig;
            if (r0 < M) {
                float sc = rowscale[r0];
                *(__half2*)(C + (size_t)r0 * BN + col) =
                    __floats2half2_rn(acc[mt][nt][0] * sc, acc[mt][nt][1] * sc);
            }
            if (r1 < M) {
                float sc = rowscale[r1];
                *(__half2*)(C + (size_t)r1 * BN + col) =
                    __floats2half2_rn(acc[mt][nt][2] * sc, acc[mt][nt][3] * sc);
            }
        }
    }
}

// ---------------------------------------------------------------------------
// Layer-1 aggregation over UNSCALED h1: per-edge dinv[s] applied here.
// a1[d] = relu(dinv[d]*(sum_s dinv[s]*h1[s] + dinv[d]*h1[d]) + b1)
__global__ void k_agg1(const float* __restrict__ b1, int n) {
    int node = blockIdx.x * (blockDim.x >> 5) + (threadIdx.x >> 5);
    if (node >= n) return;
    int lane = threadIdx.x & 31;

    const uint2* h = (const uint2*)g_h1;
    const float w = g_dinv[node];

    uint2 sv = h[(size_t)node * 32 + lane];
    float2 lo = __half22float2(*(__half2*)&sv.x);
    float2 hi = __half22float2(*(__half2*)&sv.y);
    float4 acc = make_float4(w * lo.x, w * lo.y, w * hi.x, w * hi.y);

    int j = g_off[node];
    const int jend = g_off[node + 1];
    while (j < jend) {
        int cnt = min(32, jend - j);
        int sidx = 0; float dv = 0.f;
        if (lane < cnt) { sidx = g_csr[j + lane]; dv = g_dinv[sidx]; }
        int t = 0;
        for (; t + 4 <= cnt; t += 4) {
            int s0 = __shfl_sync(0xffffffffu, sidx, t);
            int s1 = __shfl_sync(0xffffffffu, sidx, t + 1);
            int s2 = __shfl_sync(0xffffffffu, sidx, t + 2);
            int s3 = __shfl_sync(0xffffffffu, sidx, t + 3);
            float f0 = __shfl_sync(0xffffffffu, dv, t);
            float f1 = __shfl_sync(0xffffffffu, dv, t + 1);
            float f2 = __shfl_sync(0xffffffffu, dv, t + 2);
            float f3 = __shfl_sync(0xffffffffu, dv, t + 3);
            uint2 v0 = h[(size_t)s0 * 32 + lane];
            uint2 v1 = h[(size_t)s1 * 32 + lane];
            uint2 v2 = h[(size_t)s2 * 32 + lane];
            uint2 v3 = h[(size_t)s3 * 32 + lane];
            float2 p0 = __half22float2(*(__half2*)&v0.x), q0 = __half22float2(*(__half2*)&v0.y);
            float2 p1 = __half22float2(*(__half2*)&v1.x), q1 = __half22float2(*(__half2*)&v1.y);
            float2 p2 = __half22float2(*(__half2*)&v2.x), q2 = __half22float2(*(__half2*)&v2.y);
            float2 p3 = __half22float2(*(__half2*)&v3.x), q3 = __half22float2(*(__half2*)&v3.y);
            acc.x = fmaf(f0, p0.x, fmaf(f1, p1.x, fmaf(f2, p2.x, fmaf(f3, p3.x, acc.x))));
            acc.y = fmaf(f0, p0.y, fmaf(f1, p1.y, fmaf(f2, p2.y, fmaf(f3, p3.y, acc.y))));
            acc.z = fmaf(f0, q0.x, fmaf(f1, q1.x, fmaf(f2, q2.x, fmaf(f3, q3.x, acc.z))));
            acc.w = fmaf(f0, q0.y, fmaf(f1, q1.y, fmaf(f2, q2.y, fmaf(f3, q3.y, acc.w))));
        }
        for (; t < cnt; t++) {
            int s0 = __shfl_sync(0xffffffffu, sidx, t);
            float f0 = __shfl_sync(0xffffffffu, dv, t);
            uint2 v0 = h[(size_t)s0 * 32 + lane];
            float2 p0 = __half22float2(*(__half2*)&v0.x), q0 = __half22float2(*(__half2*)&v0.y);
            acc.x = fmaf(f0, p0.x, acc.x);
            acc.y = fmaf(f0, p0.y, acc.y);
            acc.z = fmaf(f0, q0.x, acc.z);
            acc.w = fmaf(f0, q0.y, acc.w);
        }
        j += cnt;
    }
    float4 b = ((const float4*)b1)[lane];
    uint2 o;
    *(__half2*)&o.x = __floats2half2_rn(fmaxf(acc.x * w + b.x, 0.f),
                                        fmaxf(acc.y * w + b.y, 0.f));
    *(__half2*)&o.y = __floats2half2_rn(fmaxf(acc.z * w + b.z, 0.f),
                                        fmaxf(acc.w * w + b.w, 0.f));
    ((uint2*)g_a1)[(size_t)node * 32 + lane] = o;
}

// Layer-2 aggregation over pre-scaled h2 (fp16), fp32 out.
__global__ void k_agg2(const float* __restrict__ b2, float* __restrict__ out, int n) {
    int node = blockIdx.x * (blockDim.x >> 5) + (threadIdx.x >> 5);
    if (node >= n) return;
    int lane = threadIdx.x & 31;

    const __half2* h = (const __half2*)g_h2;
    float2 acc = __half22float2(h[(size_t)node * 32 + lane]);
    int j = g_off[node];
    const int jend = g_off[node + 1];
    while (j < jend) {
        int cnt = min(32, jend - j);
        int sidx = (lane < cnt) ? g_csr[j + lane] : 0;
        int t = 0;
        for (; t + 4 <= cnt; t += 4) {
            int s0 = __shfl_sync(0xffffffffu, sidx, t);
            int s1 = __shfl_sync(0xffffffffu, sidx, t + 1);
            int s2 = __shfl_sync(0xffffffffu, sidx, t + 2);
            int s3 = __shfl_sync(0xffffffffu, sidx, t + 3);
            float2 v0 = __half22float2(h[(size_t)s0 * 32 + lane]);
            float2 v1 = __half22float2(h[(size_t)s1 * 32 + lane]);
            float2 v2 = __half22float2(h[(size_t)s2 * 32 + lane]);
            float2 v3 = __half22float2(h[(size_t)s3 * 32 + lane]);
            acc.x += (v0.x + v1.x) + (v2.x + v3.x);
            acc.y += (v0.y + v1.y) + (v2.y + v3.y);
        }
        for (; t < cnt; t++) {
            int s0 = __shfl_sync(0xffffffffu, sidx, t);
            float2 v0 = __half22float2(h[(size_t)s0 * 32 + lane]);
            acc.x += v0.x; acc.y += v0.y;
        }
        j += cnt;
    }
    float w = g_dinv[node];
    float2 b = ((const float2*)b2)[lane];
    ((float2*)out)[(size_t)node * 32 + lane] =
        make_float2(acc.x * w + b.x, acc.y * w + b.y);
}

// ---------------------------------------------------------------------------
extern "C" void kernel_launch(void* const* d_in, const int* in_sizes, int n_in,
                              void* d_out, int out_size) {
    const void*  eidx = d_in[0];
    const float* x    = (const float*)d_in[1];
    const float* W1   = (const float*)d_in[2];
    const float* b1   = (const float*)d_in[3];
    const float* W2   = (const float*)d_in[4];
    const float* b2   = (const float*)d_in[5];
    float* out = (float*)d_out;

    const int E = in_sizes[0] / 2;
    const int N = in_sizes[1] / NF1;

    __half *p_h1, *p_a1, *p_h2;
    float  *p_dinv;
    cudaGetSymbolAddress((void**)&p_h1,   g_h1);
    cudaGetSymbolAddress((void**)&p_a1,   g_a1);
    cudaGetSymbolAddress((void**)&p_h2,   g_h2);
    cudaGetSymbolAddress((void**)&p_dinv, g_dinv);

    const int nb = (N + SCAN_ELEMS - 1) / SCAN_ELEMS;
    const int nscan = E < 2048 ? E : 2048;

    // Fork-join: side stream runs wcvt + gemm1 (independent of CSR chain).
    cudaStream_t s1;
    cudaStreamCreateWithFlags(&s1, cudaStreamNonBlocking);
    cudaEvent_t eFork, eG1;
    cudaEventCreateWithFlags(&eFork, cudaEventDisableTiming);
    cudaEventCreateWithFlags(&eG1,   cudaEventDisableTiming);

    // fork
    cudaEventRecord(eFork, 0);
    cudaStreamWaitEvent(s1, eFork, 0);

    // branch B (s1): weights + GEMM1 (unscaled)
    k_wcvt<<<(NF1 * NF1 + NF2 * NF1 + 255) / 256, 256, 0, s1>>>(W1, W2);
    gemm1_fp16<<<(N + 127) / 128, 256, 0, s1>>>(x, p_h1, N);
    cudaEventRecord(eG1, s1);

    // branch A (legacy): CSR build
    k_init<<<(N + 255) / 256, 256>>>((const long long*)eidx, nscan, N);
    k_deg<<<(E + 255) / 256, 256>>>(eidx, E);
    k_scan1<<<nb, 256>>>(N);
    k_scan2<<<1, 128>>>(nb);
    k_scan3<<<nb, 256>>>(N, E);
    k_scatter<<<(E + 255) / 256, 256>>>(E);

    // join: agg1 needs CSR (branch A) + h1 (branch B)
    cudaStreamWaitEvent(0, eG1, 0);
    k_agg1<<<(N + 7) / 8, 256>>>(b1, N);

    // layer 2 (legacy)
    gemm2_fp16<<<(N + 255) / 256, 256>>>(p_a1, p_h2, p_dinv, N);
    k_agg2<<<(N + 7) / 8, 256>>>(b2, out, N);

    cudaEventDestroy(eFork);
    cudaEventDestroy(eG1);
    cudaStreamDestroy(s1);
}

// round 9
// speedup vs baseline: 1.0579x; 1.0579x over previous
#include <cuda_runtime.h>
#include <cuda_fp16.h>
#include <cstdint>
#include <cstddef>

// ---------------------------------------------------------------------------
// GCN_21569325760838: 2-layer GCN, CSR-gather (x8-unrolled, MLP~8),
// fp16 tensor-core GEMMs (fp32 accum), fp16 intermediates, parallel scan.
//   hs1 = dinv[row] * (x @ W1)                      (fp16 mma, fp16 out)
//   a1  = relu(dinv[d]*(sum_{s in N(d)} hs1[s] + hs1[d]) + b1)   (fp16 out)
//   hs2 = dinv[row] * (a1 @ W2)                     (fp16 mma, fp16 out)
//   out = dinv[d]*(sum hs2[s] + hs2[d]) + b2        (fp32 out)
// ---------------------------------------------------------------------------

#define NMAX 100000
#define EMAX 1600000
#define NF1  128
#define NF2  64
#define SCAN_ELEMS 1024
#define SCAN_NB ((NMAX + SCAN_ELEMS - 1) / SCAN_ELEMS)

__device__ int    g_is64 = 1;
__device__ int    g_deg [NMAX];
__device__ int    g_off [NMAX + 1];
__device__ int    g_cur [NMAX];
__device__ int    g_csr [EMAX];
__device__ int    g_src32[EMAX];
__device__ int    g_dst32[EMAX];
__device__ int    g_bsum[128];
__device__ int    g_boff[128];
__device__ float  g_dinv[NMAX];
__device__ __half g_h1  [(size_t)NMAX * NF1];   // dinv-scaled x@W1
__device__ __half g_a1  [(size_t)NMAX * NF1];
__device__ __half g_h2  [(size_t)NMAX * NF2];   // dinv-scaled a1@W2
__device__ __half g_w1t [NF1 * NF1];
__device__ __half g_w2t [NF2 * NF1];

// ---------------------------------------------------------------------------
__global__ void k_init(const long long* __restrict__ p, int nscan, int n) {
    int i = blockIdx.x * blockDim.x + threadIdx.x;
    if (i < n) g_deg[i] = 0;
    if (i < nscan) {
        long long v = p[i];
        if (v < 0 || v >= (long long)n) g_is64 = 0;
    }
}

__device__ __forceinline__ void load_edge(const void* eidx, int e, int E, int& s, int& d) {
    if (g_is64) {
        const long long* p = (const long long*)eidx;
        s = (int)p[e]; d = (int)p[(size_t)E + e];
    } else {
        const int* p = (const int*)eidx;
        s = p[e]; d = p[(size_t)E + e];
    }
}

// Degree histogram + compact int32 edge copy (coalesced).
__global__ void k_deg(const void* __restrict__ eidx, int E) {
    int e = blockIdx.x * blockDim.x + threadIdx.x;
    if (e >= E) return;
    int s, d;
    load_edge(eidx, e, E, s, d);
    g_src32[e] = s;
    g_dst32[e] = d;
    atomicAdd(&g_deg[d], 1);
}

__global__ void k_wcvt(const float* __restrict__ W1, const float* __restrict__ W2) {
    int i = blockIdx.x * blockDim.x + threadIdx.x;
    if (i < NF1 * NF1) {
        int n = i / NF1, k = i % NF1;
        g_w1t[i] = __float2half(W1[(size_t)k * NF1 + n]);
    } else if (i < NF1 * NF1 + NF2 * NF1) {
        int j = i - NF1 * NF1;
        int n = j / NF1, k = j % NF1;
        g_w2t[j] = __float2half(W2[(size_t)k * NF2 + n]);
    }
}

// ---------------------------------------------------------------------------
__global__ void k_scan1(int n) {
    __shared__ int red[256];
    const int t = threadIdx.x;
    int i0 = blockIdx.x * SCAN_ELEMS + t * 4;
    int s = 0;
    #pragma unroll
    for (int k = 0; k < 4; k++) {
        int i = i0 + k;
        if (i < n) s += g_deg[i];
    }
    red[t] = s;
    __syncthreads();
    #pragma unroll
    for (int st = 128; st > 0; st >>= 1) {
        if (t < st) red[t] += red[t + st];
        __syncthreads();
    }
    if (t == 0) g_bsum[blockIdx.x] = red[0];
}

__global__ void k_scan2(int nb) {
    __shared__ int sm[128];
    const int t = threadIdx.x;
    int v = (t < nb) ? g_bsum[t] : 0;
    sm[t] = v;
    __syncthreads();
    #pragma unroll
    for (int st = 1; st < 128; st <<= 1) {
        int u = (t >= st) ? sm[t - st] : 0;
        __syncthreads();
        sm[t] += u;
        __syncthreads();
    }
    g_boff[t] = sm[t] - v;
}

__global__ void k_scan3(int n, int E) {
    __shared__ int sm[256];
    const int t = threadIdx.x;
    const int i0 = blockIdx.x * SCAN_ELEMS + t * 4;
    int vals[4];
    int s = 0;
    #pragma unroll
    for (int k = 0; k < 4; k++) {
        int i = i0 + k;
        vals[k] = (i < n) ? g_deg[i] : 0;
        s += vals[k];
    }
    sm[t] = s;
    __syncthreads();
    #pragma unroll
    for (int st = 1; st < 256; st <<= 1) {
        int u = (t >= st) ? sm[t - st] : 0;
        __syncthreads();
        sm[t] += u;
        __syncthreads();
    }
    int base = g_boff[blockIdx.x] + sm[t] - s;
    #pragma unroll
    for (int k = 0; k < 4; k++) {
        int i = i0 + k;
        if (i < n) {
            g_off[i] = base;
            g_cur[i] = base;
            g_dinv[i] = rsqrtf((float)(vals[k] + 1));
            base += vals[k];
        }
    }
    if (blockIdx.x == 0 && t == 0) g_off[n] = E;
}

__global__ void k_scatter(int E) {
    int e = blockIdx.x * blockDim.x + threadIdx.x;
    if (e >= E) return;
    int d = g_dst32[e];
    int pos = atomicAdd(&g_cur[d], 1);
    g_csr[pos] = g_src32[e];
}

// ---------------------------------------------------------------------------
// GEMM1: fp16 mma m16n8k16. C fp16 = rowscale[m]*(A_f32[M,128] @ W1).
// Block 128x128, 8 warps (2x4), warp tile 64x32.
// ---------------------------------------------------------------------------
__global__ void __launch_bounds__(256, 1)
gemm1_fp16(const float* __restrict__ A, __half* __restrict__ C,
           const float* __restrict__ rowscale, int M) {
    constexpr int BM = 128, BN = 128, KC = 32;
    constexpr int K = NF1;
    constexpr int AST = KC + 8;
    constexpr int BST = KC + 8;
    constexpr int WNUM = BN / 32;   // 4
    __shared__ __half As[BM][AST];
    __shared__ __half Bs[BN][BST];

    const int tid  = threadIdx.x;
    const int lane = tid & 31;
    const int warp = tid >> 5;
    const int gid  = lane >> 2;
    const int tig  = lane & 3;
    const int wm   = (warp / WNUM) * 64;
    const int wn   = (warp % WNUM) * 32;
    const int row0 = blockIdx.x * BM;

    float acc[4][4][4];
    #pragma unroll
    for (int mt = 0; mt < 4; mt++)
        #pragma unroll
        for (int nt = 0; nt < 4; nt++)
            #pragma unroll
            for (int i = 0; i < 4; i++) acc[mt][nt][i] = 0.f;

    for (int k0 = 0; k0 < K; k0 += KC) {
        #pragma unroll
        for (int idx = tid; idx < BM * (KC / 4); idx += 256) {
            int r = idx / (KC / 4), c4 = (idx % (KC / 4)) * 4;
            float4 v = make_float4(0.f, 0.f, 0.f, 0.f);
            if (row0 + r < M)
                v = *(const float4*)(A + (size_t)(row0 + r) * K + k0 + c4);
            uint2 o;
            *(__half2*)&o.x = __floats2half2_rn(v.x, v.y);
            *(__half2*)&o.y = __floats2half2_rn(v.z, v.w);
            *(uint2*)&As[r][c4] = o;
        }
        #pragma unroll
        for (int idx = tid; idx < BN * (KC / 4); idx += 256) {
            int n = idx / (KC / 4), c4 = (idx % (KC / 4)) * 4;
            *(uint2*)&Bs[n][c4] = *(const uint2*)(g_w1t + (size_t)n * K + k0 + c4);
        }
        __syncthreads();

        #pragma unroll
        for (int ks = 0; ks < KC / 16; ks++) {
            const int kk = ks * 16;
            uint32_t af[4][4];
            #pragma unroll
            for (int mt = 0; mt < 4; mt++) {
                int rb = wm + mt * 16 + gid;
                af[mt][0] = *(const uint32_t*)&As[rb    ][kk + 2 * tig];
                af[mt][1] = *(const uint32_t*)&As[rb + 8][kk + 2 * tig];
                af[mt][2] = *(const uint32_t*)&As[rb    ][kk + 2 * tig + 8];
                af[mt][3] = *(const uint32_t*)&As[rb + 8][kk + 2 * tig + 8];
            }
            uint32_t bf[4][2];
            #pragma unroll
            for (int nt = 0; nt < 4; nt++) {
                int cb = wn + nt * 8 + gid;
                bf[nt][0] = *(const uint32_t*)&Bs[cb][kk + 2 * tig];
                bf[nt][1] = *(const uint32_t*)&Bs[cb][kk + 2 * tig + 8];
            }
            #pragma unroll
            for (int mt = 0; mt < 4; mt++)
                #pragma unroll
                for (int nt = 0; nt < 4; nt++) {
                    asm volatile(
                        "mma.sync.aligned.m16n8k16.row.col.f32.f16.f16.f32 "
                        "{%0,%1,%2,%3}, {%4,%5,%6,%7}, {%8,%9}, {%0,%1,%2,%3};\n"
                        : "+f"(acc[mt][nt][0]), "+f"(acc[mt][nt][1]),
                          "+f"(acc[mt][nt][2]), "+f"(acc[mt][nt][3])
                        : "r"(af[mt][0]), "r"(af[mt][1]),
                          "r"(af[mt][2]), "r"(af[mt][3]),
                          "r"(bf[nt][0]), "r"(bf[nt][1]));
                }
        }
        __syncthreads();
    }

    #pragma unroll
    for (int mt = 0; mt < 4; mt++) {
        int r0 = row0 + wm + mt * 16 + gid;
        int r1 = r0 + 8;
        #pragma unroll
        for (int nt = 0; nt < 4; nt++) {
            int col = wn + nt * 8 + 2 * tig;
            if (r0 < M) {
                float sc = rowscale[r0];
                *(__half2*)(C + (size_t)r0 * BN + col) =
                    __floats2half2_rn(acc[mt][nt][0] * sc, acc[mt][nt][1] * sc);
            }
            if (r1 < M) {
                float sc = rowscale[r1];
                *(__half2*)(C + (size_t)r1 * BN + col) =
                    __floats2half2_rn(acc[mt][nt][2] * sc, acc[mt][nt][3] * sc);
            }
        }
    }
}

// ---------------------------------------------------------------------------
// GEMM2: fp16 mma m16n8k16, C fp16 = rowscale[m]*(A_f16[M,128] @ W2).
// Block 256x64, 8 warps (4x2), warp tile 64x32.
// ---------------------------------------------------------------------------
__global__ void __launch_bounds__(256, 1)
gemm2_fp16(const __half* __restrict__ A, __half* __restrict__ C,
           const float* __restrict__ rowscale, int M) {
    constexpr int BM = 256, BN = 64, KC = 32;
    constexpr int K = NF1;
    constexpr int AST = KC + 8;
    constexpr int BST = KC + 8;
    constexpr int WNUM = BN / 32;  // 2
    __shared__ __half As[BM][AST];
    __shared__ __half Bs[BN][BST];

    const int tid  = threadIdx.x;
    const int lane = tid & 31;
    const int warp = tid >> 5;
    const int gid  = lane >> 2;
    const int tig  = lane & 3;
    const int wm   = (warp / WNUM) * 64;
    const int wn   = (warp % WNUM) * 32;
    const int row0 = blockIdx.x * BM;

    float acc[4][4][4];
    #pragma unroll
    for (int mt = 0; mt < 4; mt++)
        #pragma unroll
        for (int nt = 0; nt < 4; nt++)
            #pragma unroll
            for (int i = 0; i < 4; i++) acc[mt][nt][i] = 0.f;

    for (int k0 = 0; k0 < K; k0 += KC) {
        #pragma unroll
        for (int idx = tid; idx < BM * (KC / 4); idx += 256) {
            int r = idx / (KC / 4), c4 = (idx % (KC / 4)) * 4;
            uint2 v = make_uint2(0u, 0u);
            if (row0 + r < M)
                v = *(const uint2*)(A + (size_t)(row0 + r) * K + k0 + c4);
            *(uint2*)&As[r][c4] = v;
        }
        #pragma unroll
        for (int idx = tid; idx < BN * (KC / 4); idx += 256) {
            int n = idx / (KC / 4), c4 = (idx % (KC / 4)) * 4;
            *(uint2*)&Bs[n][c4] = *(const uint2*)(g_w2t + (size_t)n * K + k0 + c4);
        }
        __syncthreads();

        #pragma unroll
        for (int ks = 0; ks < KC / 16; ks++) {
            const int kk = ks * 16;
            uint32_t af[4][4];
            #pragma unroll
            for (int mt = 0; mt < 4; mt++) {
                int rb = wm + mt * 16 + gid;
                af[mt][0] = *(const uint32_t*)&As[rb    ][kk + 2 * tig];
                af[mt][1] = *(const uint32_t*)&As[rb + 8][kk + 2 * tig];
                af[mt][2] = *(const uint32_t*)&As[rb    ][kk + 2 * tig + 8];
                af[mt][3] = *(const uint32_t*)&As[rb + 8][kk + 2 * tig + 8];
            }
            uint32_t bf[4][2];
            #pragma unroll
            for (int nt = 0; nt < 4; nt++) {
                int cb = wn + nt * 8 + gid;
                bf[nt][0] = *(const uint32_t*)&Bs[cb][kk + 2 * tig];
                bf[nt][1] = *(const uint32_t*)&Bs[cb][kk + 2 * tig + 8];
            }
            #pragma unroll
            for (int mt = 0; mt < 4; mt++)
                #pragma unroll
                for (int nt = 0; nt < 4; nt++) {
                    asm volatile(
                        "mma.sync.aligned.m16n8k16.row.col.f32.f16.f16.f32 "
                        "{%0,%1,%2,%3}, {%4,%5,%6,%7}, {%8,%9}, {%0,%1,%2,%3};\n"
                        : "+f"(acc[mt][nt][0]), "+f"(acc[mt][nt][1]),
                          "+f"(acc[mt][nt][2]), "+f"(acc[mt][nt][3])
                        : "r"(af[mt][0]), "r"(af[mt][1]),
                          "r"(af[mt][2]), "r"(af[mt][3]),
                          "r"(bf[nt][0]), "r"(bf[nt][1]));
                }
        }
        __syncthreads();
    }

    #pragma unroll
    for (int mt = 0; mt < 4; mt++) {
        int r0 = row0 + wm + mt * 16 + gid;
        int r1 = r0 + 8;
        #pragma unroll
        for (int nt = 0; nt < 4; nt++) {
            int col = wn + nt * 8 + 2 * tig;
            if (r0 < M) {
                float sc = rowscale[r0];
                *(__half2*)(C + (size_t)r0 * BN + col) =
                    __floats2half2_rn(acc[mt][nt][0] * sc, acc[mt][nt][1] * sc);
            }
            if (r1 < M) {
                float sc = rowscale[r1];
                *(__half2*)(C + (size_t)r1 * BN + col) =
                    __floats2half2_rn(acc[mt][nt][2] * sc, acc[mt][nt][3] * sc);
            }
        }
    }
}

// ---------------------------------------------------------------------------
// Layer-1 aggregation: warp per dst node over pre-scaled h1.
// x8-unrolled gather (8 independent row loads in flight).
__global__ void k_agg1(const float* __restrict__ b1, int n) {
    int node = blockIdx.x * (blockDim.x >> 5) + (threadIdx.x >> 5);
    if (node >= n) return;
    int lane = threadIdx.x & 31;

    const uint2* h = (const uint2*)g_h1;
    uint2 sv = h[(size_t)node * 32 + lane];
    float2 lo = __half22float2(*(__half2*)&sv.x);
    float2 hi = __half22float2(*(__half2*)&sv.y);
    float4 acc = make_float4(lo.x, lo.y, hi.x, hi.y);

    int j = g_off[node];
    const int jend = g_off[node + 1];
    while (j < jend) {
        int cnt = min(32, jend - j);
        int sidx = (lane < cnt) ? g_csr[j + lane] : 0;
        int t = 0;
        for (; t + 8 <= cnt; t += 8) {
            int s0 = __shfl_sync(0xffffffffu, sidx, t);
            int s1 = __shfl_sync(0xffffffffu, sidx, t + 1);
            int s2 = __shfl_sync(0xffffffffu, sidx, t + 2);
            int s3 = __shfl_sync(0xffffffffu, sidx, t + 3);
            int s4 = __shfl_sync(0xffffffffu, sidx, t + 4);
            int s5 = __shfl_sync(0xffffffffu, sidx, t + 5);
            int s6 = __shfl_sync(0xffffffffu, sidx, t + 6);
            int s7 = __shfl_sync(0xffffffffu, sidx, t + 7);
            uint2 v0 = h[(size_t)s0 * 32 + lane];
            uint2 v1 = h[(size_t)s1 * 32 + lane];
            uint2 v2 = h[(size_t)s2 * 32 + lane];
            uint2 v3 = h[(size_t)s3 * 32 + lane];
            uint2 v4 = h[(size_t)s4 * 32 + lane];
            uint2 v5 = h[(size_t)s5 * 32 + lane];
            uint2 v6 = h[(size_t)s6 * 32 + lane];
            uint2 v7 = h[(size_t)s7 * 32 + lane];
            float2 p0 = __half22float2(*(__half2*)&v0.x), q0 = __half22float2(*(__half2*)&v0.y);
            float2 p1 = __half22float2(*(__half2*)&v1.x), q1 = __half22float2(*(__half2*)&v1.y);
            float2 p2 = __half22float2(*(__half2*)&v2.x), q2 = __half22float2(*(__half2*)&v2.y);
            float2 p3 = __half22float2(*(__half2*)&v3.x), q3 = __half22float2(*(__half2*)&v3.y);
            float2 p4 = __half22float2(*(__half2*)&v4.x), q4 = __half22float2(*(__half2*)&v4.y);
            float2 p5 = __half22float2(*(__half2*)&v5.x), q5 = __half22float2(*(__half2*)&v5.y);
            float2 p6 = __half22float2(*(__half2*)&v6.x), q6 = __half22float2(*(__half2*)&v6.y);
            float2 p7 = __half22float2(*(__half2*)&v7.x), q7 = __half22float2(*(__half2*)&v7.y);
            acc.x += ((p0.x + p1.x) + (p2.x + p3.x)) + ((p4.x + p5.x) + (p6.x + p7.x));
            acc.y += ((p0.y + p1.y) + (p2.y + p3.y)) + ((p4.y + p5.y) + (p6.y + p7.y));
            acc.z += ((q0.x + q1.x) + (q2.x + q3.x)) + ((q4.x + q5.x) + (q6.x + q7.x));
            acc.w += ((q0.y + q1.y) + (q2.y + q3.y)) + ((q4.y + q5.y) + (q6.y + q7.y));
        }
        for (; t < cnt; t++) {
            int s0 = __shfl_sync(0xffffffffu, sidx, t);
            uint2 v0 = h[(size_t)s0 * 32 + lane];
            float2 p0 = __half22float2(*(__half2*)&v0.x), q0 = __half22float2(*(__half2*)&v0.y);
            acc.x += p0.x; acc.y += p0.y; acc.z += q0.x; acc.w += q0.y;
        }
        j += cnt;
    }
    float w = g_dinv[node];
    float4 b = ((const float4*)b1)[lane];
    uint2 o;
    *(__half2*)&o.x = __floats2half2_rn(fmaxf(acc.x * w + b.x, 0.f),
                                        fmaxf(acc.y * w + b.y, 0.f));
    *(__half2*)&o.y = __floats2half2_rn(fmaxf(acc.z * w + b.z, 0.f),
                                        fmaxf(acc.w * w + b.w, 0.f));
    ((uint2*)g_a1)[(size_t)node * 32 + lane] = o;
}

// Layer-2 aggregation: warp per dst node; x8-unrolled; fp32 out.
__global__ void k_agg2(const float* __restrict__ b2, float* __restrict__ out, int n) {
    int node = blockIdx.x * (blockDim.x >> 5) + (threadIdx.x >> 5);
    if (node >= n) return;
    int lane = threadIdx.x & 31;

    const __half2* h = (const __half2*)g_h2;
    float2 acc = __half22float2(h[(size_t)node * 32 + lane]);
    int j = g_off[node];
    const int jend = g_off[node + 1];
    while (j < jend) {
        int cnt = min(32, jend - j);
        int sidx = (lane < cnt) ? g_csr[j + lane] : 0;
        int t = 0;
        for (; t + 8 <= cnt; t += 8) {
            int s0 = __shfl_sync(0xffffffffu, sidx, t);
            int s1 = __shfl_sync(0xffffffffu, sidx, t + 1);
            int s2 = __shfl_sync(0xffffffffu, sidx, t + 2);
            int s3 = __shfl_sync(0xffffffffu, sidx, t + 3);
            int s4 = __shfl_sync(0xffffffffu, sidx, t + 4);
            int s5 = __shfl_sync(0xffffffffu, sidx, t + 5);
            int s6 = __shfl_sync(0xffffffffu, sidx, t + 6);
            int s7 = __shfl_sync(0xffffffffu, sidx, t + 7);
            float2 v0 = __half22float2(h[(size_t)s0 * 32 + lane]);
            float2 v1 = __half22float2(h[(size_t)s1 * 32 + lane]);
            float2 v2 = __half22float2(h[(size_t)s2 * 32 + lane]);
            float2 v3 = __half22float2(h[(size_t)s3 * 32 + lane]);
            float2 v4 = __half22float2(h[(size_t)s4 * 32 + lane]);
            float2 v5 = __half22float2(h[(size_t)s5 * 32 + lane]);
            float2 v6 = __half22float2(h[(size_t)s6 * 32 + lane]);
            float2 v7 = __half22float2(h[(size_t)s7 * 32 + lane]);
            acc.x += ((v0.x + v1.x) + (v2.x + v3.x)) + ((v4.x + v5.x) + (v6.x + v7.x));
            acc.y += ((v0.y + v1.y) + (v2.y + v3.y)) + ((v4.y + v5.y) + (v6.y + v7.y));
        }
        for (; t < cnt; t++) {
            int s0 = __shfl_sync(0xffffffffu, sidx, t);
            float2 v0 = __half22float2(h[(size_t)s0 * 32 + lane]);
            acc.x += v0.x; acc.y += v0.y;
        }
        j += cnt;
    }
    float w = g_dinv[node];
    float2 b = ((const float2*)b2)[lane];
    ((float2*)out)[(size_t)node * 32 + lane] =
        make_float2(acc.x * w + b.x, acc.y * w + b.y);
}

// ---------------------------------------------------------------------------
extern "C" void kernel_launch(void* const* d_in, const int* in_sizes, int n_in,
                              void* d_out, int out_size) {
    const void*  eidx = d_in[0];
    const float* x    = (const float*)d_in[1];
    const float* W1   = (const float*)d_in[2];
    const float* b1   = (const float*)d_in[3];
    const float* W2   = (const float*)d_in[4];
    const float* b2   = (const float*)d_in[5];
    float* out = (float*)d_out;

    const int E = in_sizes[0] / 2;
    const int N = in_sizes[1] / NF1;

    __half *p_h1, *p_a1, *p_h2;
    float  *p_dinv;
    cudaGetSymbolAddress((void**)&p_h1,   g_h1);
    cudaGetSymbolAddress((void**)&p_a1,   g_a1);
    cudaGetSymbolAddress((void**)&p_h2,   g_h2);
    cudaGetSymbolAddress((void**)&p_dinv, g_dinv);

    const int nb = (N + SCAN_ELEMS - 1) / SCAN_ELEMS;
    const int nscan = E < 2048 ? E : 2048;

    k_init<<<(N + 255) / 256, 256>>>((const long long*)eidx, nscan, N);
    k_deg<<<(E + 255) / 256, 256>>>(eidx, E);
    k_wcvt<<<(NF1 * NF1 + NF2 * NF1 + 255) / 256, 256>>>(W1, W2);
    k_scan1<<<nb, 256>>>(N);
    k_scan2<<<1, 128>>>(nb);
    k_scan3<<<nb, 256>>>(N, E);
    k_scatter<<<(E + 255) / 256, 256>>>(E);

    // layer 1
    gemm1_fp16<<<(N + 127) / 128, 256>>>(x, p_h1, p_dinv, N);
    k_agg1<<<(N + 7) / 8, 256>>>(b1, N);

    // layer 2
    gemm2_fp16<<<(N + 255) / 256, 256>>>(p_a1, p_h2, p_dinv, N);
    k_agg2<<<(N + 7) / 8, 256>>>(b2, out, N);
}